// round 2
// baseline (speedup 1.0000x reference)
#include <cuda_runtime.h>
#include <cstdint>

// ---- problem constants ----
#define K_VOL 27
#define HALFK 1
#define SENC 258                 // COORD_RANGE + 2*HALF
#define NK_MAX 2700000           // 100000 * 27
#define TAB_BITS 23
#define TAB (1u << TAB_BITS)     // 8M slots
#define TMASK (TAB - 1u)
#define SCAN_TILE 2048
#define NBLK_MAX ((NK_MAX + SCAN_TILE - 1) / SCAN_TILE)  // 1319

// ---- static device scratch (no allocations allowed) ----
__device__ int g_ht_key[TAB];        // -1 = empty
__device__ int g_ht_val[TAB];        // min flat index for key
__device__ int g_enc[NK_MAX];        // encoding per entry
__device__ int g_slot[NK_MAX];       // hash slot, then overwritten with minidx
__device__ int g_scan[NK_MAX];       // flags -> inclusive scan
__device__ int g_bsum[4096];         // block sums for scan

// 1) clear hash table (int4 vectorized)
__global__ void k_init() {
    unsigned i = blockIdx.x * blockDim.x + threadIdx.x;
    if (i * 4 < TAB) {
        ((int4*)g_ht_key)[i] = make_int4(-1, -1, -1, -1);
        ((int4*)g_ht_val)[i] = make_int4(0x7fffffff, 0x7fffffff, 0x7fffffff, 0x7fffffff);
    }
}

// 2) encode + hash insert + atomicMin of flat index
__global__ void k_build(const int* __restrict__ si, int N, int NK) {
    int i = blockIdx.x * blockDim.x + threadIdx.x;
    if (i >= NK) return;
    int n = i / K_VOL;
    int k = i - n * K_VOL;
    int b = si[n];
    // shifted coords: coord + offset + HALF, offset = (k/9 -1, (k/3)%3 -1, k%3 -1)
    int x = si[N + n]     + (k / 9);
    int y = si[2 * N + n] + ((k / 3) % 3);
    int z = si[3 * N + n] + (k % 3);
    int enc = ((b * SENC + x) * SENC + y) * SENC + z;

    unsigned h = ((unsigned)enc * 2654435761u) >> (32 - TAB_BITS);
    for (;;) {
        int cur = g_ht_key[h];
        if (cur == enc) break;
        if (cur == -1) {
            cur = atomicCAS(&g_ht_key[h], -1, enc);
            if (cur == -1 || cur == enc) break;
        }
        h = (h + 1) & TMASK;
    }
    atomicMin(&g_ht_val[h], i);
    g_enc[i]  = enc;
    g_slot[i] = (int)h;
}

// 3) resolve min index per entry; flags
__global__ void k_flag(int NK) {
    int i = blockIdx.x * blockDim.x + threadIdx.x;
    if (i >= NK) return;
    int m = g_ht_val[g_slot[i]];
    g_slot[i] = m;               // slot[] now holds minidx
    g_scan[i] = (m == i) ? 1 : 0;
}

// 4a) per-block inclusive scan over SCAN_TILE elements
__global__ void k_scan1(int NK) {
    __shared__ int sm[256];
    int t = threadIdx.x;
    int base = blockIdx.x * SCAN_TILE + t * 8;
    int v[8];
    int run = 0;
#pragma unroll
    for (int j = 0; j < 8; j++) {
        int idx = base + j;
        int f = (idx < NK) ? g_scan[idx] : 0;
        run += f;
        v[j] = run;
    }
    sm[t] = run;
    __syncthreads();
    for (int off = 1; off < 256; off <<= 1) {
        int add = (t >= off) ? sm[t - off] : 0;
        __syncthreads();
        sm[t] += add;
        __syncthreads();
    }
    int excl = sm[t] - run;
#pragma unroll
    for (int j = 0; j < 8; j++) {
        int idx = base + j;
        if (idx < NK) g_scan[idx] = v[j] + excl;
    }
    if (t == 255) g_bsum[blockIdx.x] = sm[255];
}

// 4b) scan block sums (single block, up to 2048 blocks)
__global__ void k_scan2(int nblk) {
    __shared__ int tot[1024];
    int t = threadIdx.x;
    int a = (2 * t     < nblk) ? g_bsum[2 * t]     : 0;
    int b = (2 * t + 1 < nblk) ? g_bsum[2 * t + 1] : 0;
    int s0 = a, s1 = a + b;
    tot[t] = s1;
    __syncthreads();
    for (int off = 1; off < 1024; off <<= 1) {
        int add = (t >= off) ? tot[t - off] : 0;
        __syncthreads();
        tot[t] += add;
        __syncthreads();
    }
    int excl = tot[t] - s1;
    if (2 * t     < nblk) g_bsum[2 * t]     = s0 + excl;
    if (2 * t + 1 < nblk) g_bsum[2 * t + 1] = s1 + excl;
}

// 4c) add block offsets
__global__ void k_scan3(int NK) {
    int blk = blockIdx.x;
    if (blk == 0) return;
    int add = g_bsum[blk - 1];
    int base = blk * SCAN_TILE + threadIdx.x * 8;
#pragma unroll
    for (int j = 0; j < 8; j++) {
        int idx = base + j;
        if (idx < NK) g_scan[idx] += add;
    }
}

// 5) kernel_map rows + out_key for winners
__global__ void k_emit(int NK, float* __restrict__ out_km, float* __restrict__ out_ok) {
    int i = blockIdx.x * blockDim.x + threadIdx.x;
    if (i >= NK) return;
    int m = g_slot[i];
    int u = g_scan[m] - 1;
    int n = i / K_VOL;
    float* km = out_km + (size_t)3 * i;
    km[0] = (float)n;
    km[1] = (float)u;
    km[2] = (float)(i - n * K_VOL);
    if (m == i) {
        int enc = g_enc[i];
        int z = enc % SENC;
        int r = enc / SENC;
        int y = r % SENC;
        int x = (r / SENC) % SENC;
        float* ok = out_ok + (size_t)3 * u;
        ok[0] = (float)(x - HALFK);
        ok[1] = (float)(y - HALFK);
        ok[2] = (float)(z - HALFK);
    }
}

// 6) winner feature rows: direct float4 copy, 8 lanes per entry
__global__ void k_featw(int NK, const float4* __restrict__ feat, float4* __restrict__ outf) {
    long long tid = (long long)blockIdx.x * blockDim.x + threadIdx.x;
    int i = (int)(tid >> 3);
    int lane = (int)(tid & 7);
    if (i >= NK) return;
    if (g_slot[i] != i) return;
    int u = g_scan[i] - 1;
    int n = i / K_VOL;
    outf[(size_t)u * 8 + lane] = feat[(size_t)n * 8 + lane];
}

// 7) duplicate entries: atomicAdd into winner rows (runs after k_featw)
__global__ void k_featd(int NK, const float* __restrict__ feat, float* __restrict__ outf) {
    int i = blockIdx.x * blockDim.x + threadIdx.x;
    if (i >= NK) return;
    int m = g_slot[i];
    if (m == i) return;
    int u = g_scan[m] - 1;
    int n = i / K_VOL;
    const float* src = feat + (size_t)n * 32;
    float* dst = outf + (size_t)u * 32;
#pragma unroll
    for (int c = 0; c < 32; c++) atomicAdd(dst + c, src[c]);
}

// 8) pad tail rows [U, NK): out_key = -1, out_feats = 0
__global__ void k_tail(int NK, float* __restrict__ out_ok, float* __restrict__ out_of) {
    int r = blockIdx.x * blockDim.x + threadIdx.x;
    if (r >= NK) return;
    int U = g_scan[NK - 1];
    if (r < U) return;
    float* ok = out_ok + (size_t)3 * r;
    ok[0] = -1.0f; ok[1] = -1.0f; ok[2] = -1.0f;
    float* of = out_of + (size_t)32 * r;
#pragma unroll
    for (int c = 0; c < 32; c++) of[c] = 0.0f;
}

extern "C" void kernel_launch(void* const* d_in, const int* in_sizes, int n_in,
                              void* d_out, int out_size) {
    const int* si = (const int*)d_in[0];          // [4, N]
    const float* feat = (const float*)d_in[1];    // [N, 32]
    int N = in_sizes[0] / 4;
    int NK = N * K_VOL;

    float* out = (float*)d_out;
    // layout: kernel_map [NK,3] | out_key [NK,3] | out_feats [NK,32]
    float* out_km = out;
    float* out_ok = out + (size_t)3 * NK;
    float* out_of = out + (size_t)6 * NK;

    const int T = 256;
    int gNK = (NK + T - 1) / T;
    int nblk = (NK + SCAN_TILE - 1) / SCAN_TILE;

    k_init<<<(TAB / 4 + T - 1) / T, T>>>();
    k_build<<<gNK, T>>>(si, N, NK);
    k_flag<<<gNK, T>>>(NK);
    k_scan1<<<nblk, T>>>(NK);
    k_scan2<<<1, 1024>>>(nblk);
    k_scan3<<<nblk, T>>>(NK);
    k_emit<<<gNK, T>>>(NK, out_km, out_ok);
    {
        long long lanes = (long long)NK * 8;
        int g = (int)((lanes + T - 1) / T);
        k_featw<<<g, T>>>(NK, (const float4*)feat, (float4*)out_of);
    }
    k_featd<<<gNK, T>>>(NK, feat, out_of);
    k_tail<<<gNK, T>>>(NK, out_ok, out_of);
}